// round 3
// baseline (speedup 1.0000x reference)
#include <cuda_runtime.h>
#include <cstdint>

// Problem constants
static constexpr int N_ = 1024;
static constexpr int K_ = 32;
static constexpr int I_ = 10000;
static constexpr int I4_ = I_ / 4;       // 2500 float4 chunks per row

__device__ __forceinline__ float lg2_approx(float v) {
    float r; asm("lg2.approx.f32 %0, %1;" : "=f"(r) : "f"(v)); return r;
}
__device__ __forceinline__ float ex2_approx(float v) {
    float r; asm("ex2.approx.f32 %0, %1;" : "=f"(r) : "f"(v)); return r;
}
// f32x2 packed helpers (sm_103a FFMA2 path — ptxas never emits these from C++)
__device__ __forceinline__ uint64_t pk(float lo, float hi) {
    uint64_t r; asm("mov.b64 %0, {%1, %2};" : "=l"(r) : "f"(lo), "f"(hi)); return r;
}
__device__ __forceinline__ void upk(uint64_t v, float& lo, float& hi) {
    asm("mov.b64 {%0, %1}, %2;" : "=f"(lo), "=f"(hi) : "l"(v));
}
__device__ __forceinline__ uint64_t fma2(uint64_t a, uint64_t b, uint64_t c) {
    uint64_t d; asm("fma.rn.f32x2 %0, %1, %2, %3;" : "=l"(d) : "l"(a), "l"(b), "l"(c)); return d;
}
__device__ __forceinline__ uint64_t add2(uint64_t a, uint64_t b) {
    uint64_t d; asm("add.rn.f32x2 %0, %1, %2;" : "=l"(d) : "l"(a), "l"(b)); return d;
}

// out[n,k] = (sum_i x*w) / (sum_i w),   w = 2^( cs*logits - 0.1*log2(t) ),
// t = -ln(u).  With L = lg2(u):  log2(t) = log2(-L) + log2(ln2).
// Decompose -L (always a positive normal for u in (0,1)) via exponent/mantissa
// bit tricks:  log2(-L) = (bits*2^-23 - 127) + D(m),  m = mantissa in [1,2),
// D(m) = log2(m) - (m-1), approximated by a degree-5 poly in m whose
// coefficients are pre-scaled by -0.1 (the 1/temperature in log2 domain):
//   G(m) = -0.1*D(m) - g0,  g0 folded into CB.
// CB = 12.7 (from -0.1*(-127)) + 0.1789187 (g0) + 0.05287663 (-0.1*log2(ln2)).
// FMNMX clamp on the exponent term guards lg2.approx underflow to +/-0 at
// u -> 1 (without it, w would blow up to ~2^13 on ~20 elements).
__global__ void __launch_bounds__(1024, 1)
concrete_selector_kernel(const float* __restrict__ x,
                         const float* __restrict__ u,
                         const float* __restrict__ logits,
                         float* __restrict__ out) {
    __shared__ __align__(16) float xs[I_];   // x row for this n, reused by 32 warps

    const int n   = blockIdx.x;
    const int tid = threadIdx.x;

    // Cooperative load of x[n, :] into shared (float4)
    {
        const float4* __restrict__ xg4 =
            reinterpret_cast<const float4*>(x + (size_t)n * I_);
        float4* xs4 = reinterpret_cast<float4*>(xs);
        for (int i = tid; i < I4_; i += 1024) xs4[i] = xg4[i];
    }
    __syncthreads();

    const int warp = tid >> 5;
    const int lane = tid & 31;
    const int k    = warp;    // 32 warps == 32 k's

    const float4* __restrict__ ug4 =
        reinterpret_cast<const float4*>(u + ((size_t)n * K_ + k) * (size_t)I_);
    const float4* __restrict__ cg4 =
        reinterpret_cast<const float4*>(logits + (size_t)k * I_);
    const uint64_t* __restrict__ xs2 = reinterpret_cast<const uint64_t*>(xs);

    // Packed constants (splat)
    const uint64_t G5 = pk(-4.32743e-3f,  -4.32743e-3f);
    const uint64_t G4 = pk( 4.044865e-2f,  4.044865e-2f);
    const uint64_t G3 = pk(-1.595078e-1f, -1.595078e-1f);
    const uint64_t G2 = pk( 3.497547e-1f,  3.497547e-1f);
    const uint64_t G1 = pk(-4.0528685e-1f,-4.0528685e-1f);
    const uint64_t CH = pk(-1.1920929e-8f,-1.1920929e-8f);  // -0.1 * 2^-23
    const uint64_t CB = pk( 1.29317951e1f, 1.29317951e1f);  // 12.7+g0+(-0.1)log2(ln2)
    const uint64_t CS = pk( 4.3280850e-1f, 4.3280850e-1f);  // 3/(10*ln2)

    uint64_t accA2 = 0;   // packed pair of partial sums of x*w
    uint64_t accB2 = 0;   // packed pair of partial sums of w

    auto pbody = [&](float u0, float u1, float l0, float l1, uint64_t xp) {
        float L0 = lg2_approx(u0);                 // MUFU (u<1 -> L<0)
        float L1 = lg2_approx(u1);
        int   b0 = __float_as_int(L0);
        int   b1 = __float_as_int(L1);
        float m0 = __int_as_float((b0 & 0x007fffff) | 0x3f800000);  // LOP3
        float m1 = __int_as_float((b1 & 0x007fffff) | 0x3f800000);
        float c0 = (float)(b0 & 0x7fffffff);       // LOP3 + I2F: bits of -L
        float c1 = (float)(b1 & 0x7fffffff);
        c0 = fmaxf(c0, 8.4e8f);                    // clamp: lg2 underflow guard
        c1 = fmaxf(c1, 8.4e8f);
        uint64_t mp = pk(m0, m1);
        uint64_t cp = pk(c0, c1);
        uint64_t lp = pk(l0, l1);
        uint64_t r  = fma2(mp, G5, G4);
        r           = fma2(mp, r, G3);
        r           = fma2(mp, r, G2);
        r           = fma2(mp, r, G1);
        uint64_t hb = fma2(cp, CH, CB);
        uint64_t sv = fma2(lp, CS, hb);
        uint64_t s2 = fma2(mp, r, sv);             // full log2-score (pair)
        float sa, sb; upk(s2, sa, sb);
        uint64_t wp = pk(ex2_approx(sa), ex2_approx(sb));   // MUFU x2
        accB2 = add2(accB2, wp);
        accA2 = fma2(xp, wp, accA2);
    };

    constexpr int MAIN = (I4_ / 32) * 32;   // 2496: uniform main loop
    #pragma unroll 2
    for (int j = lane; j < MAIN; j += 32) {
        float4 uu = __ldcs(&ug4[j]);   // streaming: protect L2 for logits
        float4 cc = cg4[j];
        uint64_t xlo = xs2[2 * j];
        uint64_t xhi = xs2[2 * j + 1];
        pbody(uu.x, uu.y, cc.x, cc.y, xlo);
        pbody(uu.z, uu.w, cc.z, cc.w, xhi);
    }
    // Tail: chunks 2496..2499 handled by lanes 0..3
    if (lane < I4_ - MAIN) {
        int j = MAIN + lane;
        float4 uu = __ldcs(&ug4[j]);
        float4 cc = cg4[j];
        uint64_t xlo = xs2[2 * j];
        uint64_t xhi = xs2[2 * j + 1];
        pbody(uu.x, uu.y, cc.x, cc.y, xlo);
        pbody(uu.z, uu.w, cc.z, cc.w, xhi);
    }

    // Collapse packed accumulators, then warp reduction
    float a0, a1, bb0, bb1;
    upk(accA2, a0, a1);
    upk(accB2, bb0, bb1);
    float accA = a0 + a1;
    float accB = bb0 + bb1;
    #pragma unroll
    for (int off = 16; off > 0; off >>= 1) {
        accA += __shfl_down_sync(0xffffffffu, accA, off);
        accB += __shfl_down_sync(0xffffffffu, accB, off);
    }
    if (lane == 0) {
        out[(size_t)n * K_ + k] = accA / accB;
    }
}

extern "C" void kernel_launch(void* const* d_in, const int* in_sizes, int n_in,
                              void* d_out, int out_size) {
    const float* x      = (const float*)d_in[0];   // (1024, 10000)
    const float* u      = (const float*)d_in[1];   // (1024, 32, 10000)
    const float* logits = (const float*)d_in[2];   // (32, 10000)
    float* out = (float*)d_out;                    // (1024, 32)
    (void)in_sizes; (void)n_in; (void)out_size;

    concrete_selector_kernel<<<N_, 1024>>>(x, u, logits, out);
}